// round 14
// baseline (speedup 1.0000x reference)
#include <cuda_runtime.h>
#include <cstdint>

// Q8.8 SiLU via sigmoid LUT — exact magic-number pipeline + 16-copy bank-private
// u8 LUT (64 KB) so TWO blocks fit per SM (64 warps = full occupancy).
//
// Math (all steps exact / RNE-equivalent to the reference, proofs R7/R9):
//   g  = fmaf(x,256,MAGIC); qf = g-MAGIC  == RNE(x*256) (Q8.8 quantize)
//   idx = clamp(bits(g)-IDX_K, 0, 4096)   == clamp(x_q,-2048,2048)+2048
//   s   = (idx>=thr) ? 256 : u8tab[idx]   (u8tab = min(s_q,255); thr = start of
//                                          the contiguous s_q==256 plateau)
//   p  = qf * (float)s                    (exact: |qf*s| <= 32767*256 < 2^23)
//   yf = fmaf(p, 1/256, MAGIC) - MAGIC    == RNE(x_q*s_q >> 8)
//   out = yf * (1/256)                    (exact dequant)
//
// LUT layout (16 copies): entry i for lane l at byte (i>>2)*64 + (l&15)*4 + (i&3).
// Lanes l and l+16 share a copy; they collide only when (idx>>2) parities match
// => expected ~1.5 wavefronts per LDS (vs ~3.4 for a single shared copy).
//
// Table dtype probed at runtime (harness widens int16; probe words 1024/1025).

#define THREADS   1024
#define TABLE_N   4097
#define UNROLL    4
#define COPIES    16
#define LUT_BYTES (4096 * COPIES)      // 65536

#define MAGIC   12582912.0f            // 1.5 * 2^23
#define MAGIC_I 0x4B400000             // bits(MAGIC)
#define IDX_K   (MAGIC_I - 2048)       // bits(g) - IDX_K == qf + 2048

__device__ __forceinline__ int probe_mode(const void* table) {
    unsigned w0 = ((const unsigned*)table)[1024];
    unsigned w1 = ((const unsigned*)table)[1025];
    if (w0 < 0x10000u)      return (w1 == 0u) ? 0 : 1;   // 0=int64, 1=int32
    if (w0 < 0x01000000u)   return 2;                    // int16
    return 3;                                            // float32
}
__device__ __forceinline__ int tab_entry(const void* table, int i, int mode) {
    switch (mode) {
        case 0:  return (int)((const long long*)table)[i];
        case 1:  return ((const int*)table)[i];
        case 2:  return (int)((const short*)table)[i];
        default: return __float2int_rn(((const float*)table)[i]);
    }
}

__global__ void __launch_bounds__(THREADS, 2)
silu_lut_kernel(const float4* __restrict__ x,
                const void*   __restrict__ table,
                float4*       __restrict__ out,
                int n4)
{
    extern __shared__ unsigned char lut[];   // 64 KB: 16 bank-private copies
    __shared__ int thr_s;

    const int tid  = threadIdx.x;
    const int mode = probe_mode(table);
    if (tid == 0) thr_s = 1 << 30;
    __syncthreads();

    // ---- fill: thread tid packs entries 4*tid..4*tid+3, writes 16 copies ----
    {
        int i0 = tid * 4;                      // tid < 1024 -> covers 0..4095
        unsigned b0 = (unsigned)min(tab_entry(table, i0 + 0, mode), 255);
        unsigned b1 = (unsigned)min(tab_entry(table, i0 + 1, mode), 255);
        unsigned b2 = (unsigned)min(tab_entry(table, i0 + 2, mode), 255);
        unsigned b3 = (unsigned)min(tab_entry(table, i0 + 3, mode), 255);
        unsigned val = b0 | (b1 << 8) | (b2 << 16) | (b3 << 24);
        unsigned* row = (unsigned*)(lut + tid * 64);
#pragma unroll
        for (int c = 0; c < COPIES; c++)
            row[(c + tid) & (COPIES - 1)] = val;   // rotate to spread banks
        // find start of the s_q == 256 plateau (sigmoid monotone => contiguous)
        for (int i = tid + 1; i <= 4096; i += THREADS) {
            if (tab_entry(table, i, mode) == 256 &&
                tab_entry(table, i - 1, mode) != 256)
                atomicMin(&thr_s, i);
        }
    }
    __syncthreads();

    const int thr = thr_s;
    const unsigned char* mylut = lut + ((tid & (COPIES - 1)) << 2);

    const int stride = gridDim.x * THREADS;
    int i = blockIdx.x * THREADS + tid;

    for (; i + (UNROLL - 1) * stride < n4; i += UNROLL * stride) {
        float4 v[UNROLL];
#pragma unroll
        for (int u = 0; u < UNROLL; u++)
            v[u] = __ldcs(&x[i + u * stride]);
#pragma unroll
        for (int u = 0; u < UNROLL; u++) {
            float4 o;
            float* vi = (float*)&v[u];
            float* oi = (float*)&o;
#pragma unroll
            for (int e = 0; e < 4; e++) {
                float g  = fmaf(vi[e], 256.0f, MAGIC);
                float qf = g - MAGIC;
                int   b  = __float_as_int(g) - IDX_K;
                int  idx = min(max(b, 0), 4096);
                int idxm = min(idx, 4095);
                int    s = (int)mylut[((idxm >> 2) << 6) + (idxm & 3)];
                s = (idx >= thr) ? 256 : s;
                float p  = qf * (float)s;                          // exact
                float yf = fmaf(p, 1.0f / 256.0f, MAGIC) - MAGIC;  // RNE
                oi[e] = yf * (1.0f / 256.0f);
            }
            __stcs(&out[i + u * stride], o);
        }
    }
    for (; i < n4; i += stride) {
        float4 v = __ldcs(&x[i]);
        float4 o;
        float* vi = (float*)&v;
        float* oi = (float*)&o;
#pragma unroll
        for (int e = 0; e < 4; e++) {
            float g  = fmaf(vi[e], 256.0f, MAGIC);
            float qf = g - MAGIC;
            int   b  = __float_as_int(g) - IDX_K;
            int  idx = min(max(b, 0), 4096);
            int idxm = min(idx, 4095);
            int    s = (int)mylut[((idxm >> 2) << 6) + (idxm & 3)];
            s = (idx >= thr) ? 256 : s;
            float p  = qf * (float)s;
            float yf = fmaf(p, 1.0f / 256.0f, MAGIC) - MAGIC;
            oi[e] = yf * (1.0f / 256.0f);
        }
        __stcs(&out[i], o);
    }
}

// Tail (n not divisible by 4 — never runs on the bench shape).
__global__ void silu_lut_tail(const float* __restrict__ x,
                              const void*  __restrict__ table,
                              float*       __restrict__ out,
                              int start, int n)
{
    int mode = probe_mode(table);
    int i = start + blockIdx.x * blockDim.x + threadIdx.x;
    if (i < n) {
        float g  = fmaf(x[i], 256.0f, MAGIC);
        float qf = g - MAGIC;
        int   b  = __float_as_int(g) - IDX_K;
        int  idx = min(max(b, 0), 4096);
        int    s = tab_entry(table, idx, mode);
        float p  = qf * (float)s;
        float yf = fmaf(p, 1.0f / 256.0f, MAGIC) - MAGIC;
        out[i] = yf * (1.0f / 256.0f);
    }
}

extern "C" void kernel_launch(void* const* d_in, const int* in_sizes, int n_in,
                              void* d_out, int out_size)
{
    // Table = whichever input has the small element count (4097); x = the other.
    int xi = 0, ti = 1;
    if (n_in >= 2 && in_sizes[1] > in_sizes[0]) { xi = 1; ti = 0; }

    const float* x     = (const float*)d_in[xi];
    const void*  table = d_in[ti];
    float*       out   = (float*)d_out;

    int n  = out_size;          // numel(x) == numel(out)
    int n4 = n >> 2;

    cudaFuncSetAttribute(silu_lut_kernel,
                         cudaFuncAttributeMaxDynamicSharedMemorySize, LUT_BYTES);

    // Two blocks per SM (64 KB smem each) -> 64 warps/SM.
    int blocks = 296;
    int work_blocks = (n4 + THREADS - 1) / THREADS;
    if (work_blocks < blocks) blocks = work_blocks;
    if (blocks < 1) blocks = 1;

    if (n4 > 0)
        silu_lut_kernel<<<blocks, THREADS, LUT_BYTES>>>(
            (const float4*)x, table, (float4*)out, n4);

    int tail_start = n4 << 2;
    int tail = n - tail_start;
    if (tail > 0)
        silu_lut_tail<<<(tail + 255) / 256, 256>>>(x, table, out, tail_start, n);
}

// round 15
// speedup vs baseline: 1.0108x; 1.0108x over previous
#include <cuda_runtime.h>
#include <cstdint>

// Q8.8 SiLU via sigmoid LUT — exact magic-number pipeline + 16-copy bank-private
// u8 LUT (64 KB), two blocks per SM (64 warps).
//
// Math (all steps exact / RNE-equivalent to the reference, proofs R7/R9):
//   g  = fmaf(x,256,MAGIC); qf = g-MAGIC  == RNE(x*256) (Q8.8 quantize)
//   b  = bits(g)-IDX_K                    == x_q + 2048  (pure integer)
//   plateau: b >= thr  (thr = first index with s_q==256; valid on unclamped b)
//   s  = plateau ? 256 : u8tab[clamp(b,0,4095)]
//   p  = qf * (float)s                    (exact: |qf*s| <= 32767*256 < 2^23)
//   yf = fmaf(p, 1/256, MAGIC) - MAGIC    == RNE(x_q*s_q >> 8)
//   out = yf * (1/256)                    (exact dequant)
//
// LUT: 16 bank-private copies; entry i for lane l at byte (i>>2)*64+(l&15)*4+(i&3).
// Lanes l, l+16 share a copy -> expected ~1.5 wavefronts per LDS.
//
// Table dtype probed at runtime (harness widens int16; probe words 1024/1025).

#define THREADS   1024
#define UNROLL    4
#define COPIES    16
#define LUT_BYTES (4096 * COPIES)      // 65536

#define MAGIC   12582912.0f            // 1.5 * 2^23
#define MAGIC_I 0x4B400000             // bits(MAGIC)
#define IDX_K   (MAGIC_I - 2048)       // bits(g) - IDX_K == x_q + 2048

__device__ __forceinline__ int probe_mode(const void* table) {
    unsigned w0 = ((const unsigned*)table)[1024];
    unsigned w1 = ((const unsigned*)table)[1025];
    if (w0 < 0x10000u)      return (w1 == 0u) ? 0 : 1;   // 0=int64, 1=int32
    if (w0 < 0x01000000u)   return 2;                    // int16
    return 3;                                            // float32
}
__device__ __forceinline__ int tab_entry(const void* table, int i, int mode) {
    switch (mode) {
        case 0:  return (int)((const long long*)table)[i];
        case 1:  return ((const int*)table)[i];
        case 2:  return (int)((const short*)table)[i];
        default: return __float2int_rn(((const float*)table)[i]);
    }
}

__global__ void __launch_bounds__(THREADS, 2)
silu_lut_kernel(const float4* __restrict__ x,
                const void*   __restrict__ table,
                float4*       __restrict__ out,
                int n4)
{
    extern __shared__ unsigned char lut[];   // 64 KB: 16 bank-private copies
    __shared__ int thr_s;

    const int tid  = threadIdx.x;
    const int mode = probe_mode(table);

    // ---- plateau threshold: lane 0 binary search (table monotone) ----
    if (tid == 0) {
        int lo = 0, hi = 4096;                 // invariant: tab[hi] == 256
        if (tab_entry(table, 4096, mode) != 256) {
            thr_s = 1 << 30;                   // no plateau (defensive)
        } else {
            while (lo + 1 < hi) {
                int mid = (lo + hi) >> 1;
                if (tab_entry(table, mid, mode) == 256) hi = mid;
                else                                    lo = mid;
            }
            thr_s = hi;                        // first idx with s_q == 256
        }
    }

    // ---- fill: thread tid packs entries 4*tid..4*tid+3, writes 16 copies ----
    {
        int i0 = tid * 4;                      // tid < 1024 -> covers 0..4095
        unsigned b0 = (unsigned)min(tab_entry(table, i0 + 0, mode), 255);
        unsigned b1 = (unsigned)min(tab_entry(table, i0 + 1, mode), 255);
        unsigned b2 = (unsigned)min(tab_entry(table, i0 + 2, mode), 255);
        unsigned b3 = (unsigned)min(tab_entry(table, i0 + 3, mode), 255);
        unsigned val = b0 | (b1 << 8) | (b2 << 16) | (b3 << 24);
        unsigned* row = (unsigned*)(lut + tid * 64);
#pragma unroll
        for (int c = 0; c < COPIES; c++)
            row[(c + tid) & (COPIES - 1)] = val;   // rotate to spread banks
    }
    __syncthreads();

    const int thr = thr_s;
    const unsigned char* mylut = lut + ((tid & (COPIES - 1)) << 2);

    const int stride = gridDim.x * THREADS;
    int i = blockIdx.x * THREADS + tid;

    for (; i + (UNROLL - 1) * stride < n4; i += UNROLL * stride) {
        float4 v[UNROLL];
#pragma unroll
        for (int u = 0; u < UNROLL; u++)
            v[u] = __ldcs(&x[i + u * stride]);
#pragma unroll
        for (int u = 0; u < UNROLL; u++) {
            float4 o;
            float* vi = (float*)&v[u];
            float* oi = (float*)&o;
#pragma unroll
            for (int e = 0; e < 4; e++) {
                float g  = fmaf(vi[e], 256.0f, MAGIC);
                float qf = g - MAGIC;
                int   b  = __float_as_int(g) - IDX_K;     // x_q + 2048
                int idxm = min(max(b, 0), 4095);          // LDS-safe index
                int    s = (int)mylut[((idxm >> 2) << 6) + (idxm & 3)];
                s = (b >= thr) ? 256 : s;                 // plateau (unclamped b)
                float p  = qf * (float)s;                          // exact
                float yf = fmaf(p, 1.0f / 256.0f, MAGIC) - MAGIC;  // RNE
                oi[e] = yf * (1.0f / 256.0f);
            }
            __stcs(&out[i + u * stride], o);
        }
    }
    for (; i < n4; i += stride) {
        float4 v = __ldcs(&x[i]);
        float4 o;
        float* vi = (float*)&v;
        float* oi = (float*)&o;
#pragma unroll
        for (int e = 0; e < 4; e++) {
            float g  = fmaf(vi[e], 256.0f, MAGIC);
            float qf = g - MAGIC;
            int   b  = __float_as_int(g) - IDX_K;
            int idxm = min(max(b, 0), 4095);
            int    s = (int)mylut[((idxm >> 2) << 6) + (idxm & 3)];
            s = (b >= thr) ? 256 : s;
            float p  = qf * (float)s;
            float yf = fmaf(p, 1.0f / 256.0f, MAGIC) - MAGIC;
            oi[e] = yf * (1.0f / 256.0f);
        }
        __stcs(&out[i], o);
    }
}

// Tail (n not divisible by 4 — never runs on the bench shape).
__global__ void silu_lut_tail(const float* __restrict__ x,
                              const void*  __restrict__ table,
                              float*       __restrict__ out,
                              int start, int n)
{
    int mode = probe_mode(table);
    int i = start + blockIdx.x * blockDim.x + threadIdx.x;
    if (i < n) {
        float g  = fmaf(x[i], 256.0f, MAGIC);
        float qf = g - MAGIC;
        int   b  = __float_as_int(g) - IDX_K;
        int  idx = min(max(b, 0), 4096);
        int    s = tab_entry(table, idx, mode);
        float p  = qf * (float)s;
        float yf = fmaf(p, 1.0f / 256.0f, MAGIC) - MAGIC;
        out[i] = yf * (1.0f / 256.0f);
    }
}

extern "C" void kernel_launch(void* const* d_in, const int* in_sizes, int n_in,
                              void* d_out, int out_size)
{
    // Table = whichever input has the small element count (4097); x = the other.
    int xi = 0, ti = 1;
    if (n_in >= 2 && in_sizes[1] > in_sizes[0]) { xi = 1; ti = 0; }

    const float* x     = (const float*)d_in[xi];
    const void*  table = d_in[ti];
    float*       out   = (float*)d_out;

    int n  = out_size;          // numel(x) == numel(out)
    int n4 = n >> 2;

    cudaFuncSetAttribute(silu_lut_kernel,
                         cudaFuncAttributeMaxDynamicSharedMemorySize, LUT_BYTES);

    // Two blocks per SM (64 KB smem each) -> 64 warps/SM.
    int blocks = 296;
    int work_blocks = (n4 + THREADS - 1) / THREADS;
    if (work_blocks < blocks) blocks = work_blocks;
    if (blocks < 1) blocks = 1;

    if (n4 > 0)
        silu_lut_kernel<<<blocks, THREADS, LUT_BYTES>>>(
            (const float4*)x, table, (float4*)out, n4);

    int tail_start = n4 << 2;
    int tail = n - tail_start;
    if (tail > 0)
        silu_lut_tail<<<(tail + 255) / 256, 256>>>(x, table, out, tail_start, n);
}

// round 16
// speedup vs baseline: 1.0114x; 1.0006x over previous
#include <cuda_runtime.h>
#include <cstdint>

// Q8.8 SiLU via sigmoid LUT — exact magic-number pipeline + 32-copy fully
// bank-private u8 LUT (128 KB, one 1024-thread block per SM, 32 warps).
//
// Math (each step exact / RNE-equivalent to the reference; proofs R7/R9/R15):
//   g  = fmaf(x,256,MAGIC); qf = g-MAGIC  == RNE(x*256)      (Q8.8 quantize)
//   b  = bits(g)-IDX_K                    == x_q + 2048       (pure integer)
//   s  = (b>=thr) ? 256 : u8tab[clamp(b,0,4095)]   (thr = start of s_q==256
//                                                   plateau; u8tab=min(s_q,255))
//   p  = qf * (float)s                    (exact: |qf*s| <= 32767*256 < 2^23)
//   h  = fmaf(p, 1/256, MAGIC)            == MAGIC + RNE(x_q*s_q >> 8)
//   out= fmaf(h, 1/256, -49152)           (exact: h/256 has a 24-bit significand;
//                                          result is a multiple of 2^-8, |.|<=128)
//
// LUT: one private copy per bank. Entry i for lane l at byte
//   (i>>2)*128 + l*4 + (i&3)  ->  lane l only ever touches bank l
// => every LDS.U8 is exactly 1 wavefront for ANY index distribution.
//
// Table dtype probed at runtime (harness widens int16; probe words 1024/1025).

#define THREADS   1024
#define UNROLL    6
#define LUT_BYTES 131072               // 4096 entries * 32 copies

#define MAGIC   12582912.0f            // 1.5 * 2^23
#define MAGIC_I 0x4B400000             // bits(MAGIC)
#define IDX_K   (MAGIC_I - 2048)       // bits(g) - IDX_K == x_q + 2048
#define DEQ_C   (-49152.0f)            // -MAGIC/256

__device__ __forceinline__ int probe_mode(const void* table) {
    unsigned w0 = ((const unsigned*)table)[1024];
    unsigned w1 = ((const unsigned*)table)[1025];
    if (w0 < 0x10000u)      return (w1 == 0u) ? 0 : 1;   // 0=int64, 1=int32
    if (w0 < 0x01000000u)   return 2;                    // int16
    return 3;                                            // float32
}
__device__ __forceinline__ int tab_entry(const void* table, int i, int mode) {
    switch (mode) {
        case 0:  return (int)((const long long*)table)[i];
        case 1:  return ((const int*)table)[i];
        case 2:  return (int)((const short*)table)[i];
        default: return __float2int_rn(((const float*)table)[i]);
    }
}

__device__ __forceinline__ float silu_one(float xv, const unsigned char* mylut,
                                          int thr) {
    float g  = fmaf(xv, 256.0f, MAGIC);
    float qf = g - MAGIC;
    int   b  = __float_as_int(g) - IDX_K;          // x_q + 2048
    int idxm = min(max(b, 0), 4095);               // LDS-safe index
    int    s = (int)mylut[((idxm >> 2) << 7) + (idxm & 3)];
    s = (b >= thr) ? 256 : s;                      // plateau (unclamped b)
    float p  = qf * (float)s;                      // exact
    float h  = fmaf(p, 1.0f / 256.0f, MAGIC);      // RNE >> 8 (magic)
    return fmaf(h, 1.0f / 256.0f, DEQ_C);          // exact dequant
}

__global__ void __launch_bounds__(THREADS, 1)
silu_lut_kernel(const float4* __restrict__ x,
                const void*   __restrict__ table,
                float4*       __restrict__ out,
                int n4)
{
    extern __shared__ unsigned char lut[];   // 128 KB: 32 bank-private copies
    __shared__ int thr_s;

    const int tid  = threadIdx.x;
    const int mode = probe_mode(table);

    // ---- plateau threshold: lane 0 binary search (table monotone) ----
    if (tid == 0) {
        int lo = 0, hi = 4096;
        if (tab_entry(table, 4096, mode) != 256) {
            thr_s = 1 << 30;                   // no plateau (defensive)
        } else {
            while (lo + 1 < hi) {
                int mid = (lo + hi) >> 1;
                if (tab_entry(table, mid, mode) == 256) hi = mid;
                else                                    lo = mid;
            }
            thr_s = hi;                        // first idx with s_q == 256
        }
    }

    // ---- fill: thread tid packs entries 4*tid..4*tid+3, writes 32 copies ----
    {
        int i0 = tid * 4;                      // tid < 1024 -> covers 0..4095
        unsigned b0 = (unsigned)min(tab_entry(table, i0 + 0, mode), 255);
        unsigned b1 = (unsigned)min(tab_entry(table, i0 + 1, mode), 255);
        unsigned b2 = (unsigned)min(tab_entry(table, i0 + 2, mode), 255);
        unsigned b3 = (unsigned)min(tab_entry(table, i0 + 3, mode), 255);
        unsigned val = b0 | (b1 << 8) | (b2 << 16) | (b3 << 24);
        unsigned* row = (unsigned*)(lut + tid * 128);
#pragma unroll
        for (int l = 0; l < 32; l++)
            row[(l + tid) & 31] = val;         // rotate to avoid write conflicts
    }
    __syncthreads();

    const int thr = thr_s;
    const unsigned char* mylut = lut + ((tid & 31) << 2);   // this lane's bank

    const int stride = gridDim.x * THREADS;
    int i = blockIdx.x * THREADS + tid;

    // Main loop: 6 front-batched streaming LDG.128 per thread (MLP=6).
    for (; i + (UNROLL - 1) * stride < n4; i += UNROLL * stride) {
        float4 v[UNROLL];
#pragma unroll
        for (int u = 0; u < UNROLL; u++)
            v[u] = __ldcs(&x[i + u * stride]);
#pragma unroll
        for (int u = 0; u < UNROLL; u++) {
            float4 o;
            o.x = silu_one(v[u].x, mylut, thr);
            o.y = silu_one(v[u].y, mylut, thr);
            o.z = silu_one(v[u].z, mylut, thr);
            o.w = silu_one(v[u].w, mylut, thr);
            __stcs(&out[i + u * stride], o);
        }
    }
    for (; i < n4; i += stride) {
        float4 v = __ldcs(&x[i]);
        float4 o;
        o.x = silu_one(v.x, mylut, thr);
        o.y = silu_one(v.y, mylut, thr);
        o.z = silu_one(v.z, mylut, thr);
        o.w = silu_one(v.w, mylut, thr);
        __stcs(&out[i], o);
    }
}

// Tail (n not divisible by 4 — never runs on the bench shape).
__global__ void silu_lut_tail(const float* __restrict__ x,
                              const void*  __restrict__ table,
                              float*       __restrict__ out,
                              int start, int n)
{
    int mode = probe_mode(table);
    int i = start + blockIdx.x * blockDim.x + threadIdx.x;
    if (i < n) {
        float g  = fmaf(x[i], 256.0f, MAGIC);
        float qf = g - MAGIC;
        int   b  = __float_as_int(g) - IDX_K;
        int  idx = min(max(b, 0), 4096);
        int    s = tab_entry(table, idx, mode);
        float p  = qf * (float)s;
        float h  = fmaf(p, 1.0f / 256.0f, MAGIC);
        out[i] = fmaf(h, 1.0f / 256.0f, DEQ_C);
    }
}

extern "C" void kernel_launch(void* const* d_in, const int* in_sizes, int n_in,
                              void* d_out, int out_size)
{
    // Table = whichever input has the small element count (4097); x = the other.
    int xi = 0, ti = 1;
    if (n_in >= 2 && in_sizes[1] > in_sizes[0]) { xi = 1; ti = 0; }

    const float* x     = (const float*)d_in[xi];
    const void*  table = d_in[ti];
    float*       out   = (float*)d_out;

    int n  = out_size;          // numel(x) == numel(out)
    int n4 = n >> 2;

    cudaFuncSetAttribute(silu_lut_kernel,
                         cudaFuncAttributeMaxDynamicSharedMemorySize, LUT_BYTES);

    // One block per SM (128 KB smem each) -> 32 warps/SM, low sustained power.
    int blocks = 148;
    int work_blocks = (n4 + THREADS - 1) / THREADS;
    if (work_blocks < blocks) blocks = work_blocks;
    if (blocks < 1) blocks = 1;

    if (n4 > 0)
        silu_lut_kernel<<<blocks, THREADS, LUT_BYTES>>>(
            (const float4*)x, table, (float4*)out, n4);

    int tail_start = n4 << 2;
    int tail = n - tail_start;
    if (tail > 0)
        silu_lut_tail<<<(tail + 255) / 256, 256>>>(x, table, out, tail_start, n);
}